// round 5
// baseline (speedup 1.0000x reference)
#include <cuda_runtime.h>

#define NC 5
#define NR 14

__device__ __forceinline__ float fast_tanh(float x) {
    float r;
    asm("tanh.approx.f32 %0, %1;" : "=f"(r) : "f"(x));
    return r;
}

__device__ __forceinline__ float4 ldcs4(const float4* p) {
    float4 r;
    asm("ld.global.cs.v4.f32 {%0,%1,%2,%3}, [%4];"
        : "=f"(r.x), "=f"(r.y), "=f"(r.z), "=f"(r.w) : "l"(p));
    return r;
}

__device__ __forceinline__ void stcs4(float4* p, float4 v) {
    asm("st.global.cs.v4.f32 [%0], {%1,%2,%3,%4};"
        :: "l"(p), "f"(v.x), "f"(v.y), "f"(v.z), "f"(v.w) : "memory");
}

__global__ __launch_bounds__(256, 6) void rnn_fused_kernel(
    const float* __restrict__ chem,   // [C, M*N]
    const float* __restrict__ mu,     // [R, M*N]
    const float* __restrict__ vu,     // [R, M*N]
    const float* __restrict__ Q,      // [C, 2R]
    const float* __restrict__ Ks,     // [C, C]
    const float* __restrict__ v,      // [1, C]
    const float* __restrict__ y,      // [C]
    const float* __restrict__ z,      // [C]
    const int*   __restrict__ tptr,   // scalar time_index
    float* __restrict__ out,          // [M*N]
    int quads)                        // M*N / 4
{
    __shared__ float sA[NR], sB[NR], sBp[NR];
    __shared__ float sa[NC], sw[NC], sK[NC * NC];

    if (threadIdx.x == 0) {
        float invt = 1.0f / (float)(*tptr);
        float wreg[NC];
        #pragma unroll
        for (int c = 0; c < NC; ++c) {
            float vc = v[c];
            sa[c] = vc * y[c];
            wreg[c] = vc * z[c];
            sw[c] = wreg[c];
        }
        #pragma unroll
        for (int c = 0; c < NC; ++c)
            #pragma unroll
            for (int d = 0; d < NC; ++d)
                sK[c * NC + d] = Ks[c * NC + d];
        #pragma unroll
        for (int r = 0; r < NR; ++r) {
            float A = 0.0f, B = 0.0f;
            #pragma unroll
            for (int c = 0; c < NC; ++c) {
                A = fmaf(wreg[c], Q[c * (2 * NR) + r], A);
                B = fmaf(wreg[c], Q[c * (2 * NR) + NR + r], B);
            }
            sA[r] = A;
            sB[r] = B;
            sBp[r] = B * invt;
        }
    }
    __syncthreads();

    const int i = blockIdx.x * blockDim.x + threadIdx.x;
    if (i >= quads) return;

    const float4* ch4 = (const float4*)chem;
    const float4* mu4 = (const float4*)mu;
    const float4* vu4 = (const float4*)vu;
    float4* out4 = (float4*)out;

    float h[4] = {0.f, 0.f, 0.f, 0.f};

    // ---- chemical part, streamed: t_c = K@chem (accumulated), h += a_d*chem_d.
    // Chem loads go first (longest dependency chain: accum -> tanh).
    float t[NC][4] = {};
    #pragma unroll
    for (int d = 0; d < NC; ++d) {
        float4 xv = ldcs4(&ch4[d * quads + i]);
        float x[4] = {xv.x, xv.y, xv.z, xv.w};
        float ad = sa[d];
        #pragma unroll
        for (int c = 0; c < NC; ++c) {
            float kcd = sK[c * NC + d];
            #pragma unroll
            for (int k = 0; k < 4; ++k)
                t[c][k] = fmaf(kcd, x[k], t[c][k]);
        }
        #pragma unroll
        for (int k = 0; k < 4; ++k)
            h[k] = fmaf(ad, x[k], h[k]);
    }
    // tanh early (MUFU latency hidden behind the rule-loop loads below)
    #pragma unroll
    for (int c = 0; c < NC; ++c) {
        float wc = sw[c];
        #pragma unroll
        for (int k = 0; k < 4; ++k)
            h[k] = fmaf(wc, fast_tanh(t[c][k]), h[k]);
    }

    // ---- update-rule part: h += mu*(A - B*mu) + B'*vu
    #pragma unroll
    for (int r = 0; r < NR; ++r) {
        float4 m = ldcs4(&mu4[r * quads + i]);
        float4 u = ldcs4(&vu4[r * quads + i]);
        float Ar = sA[r], Br = sB[r], Bp = sBp[r];
        float mm[4] = {m.x, m.y, m.z, m.w};
        float uu[4] = {u.x, u.y, u.z, u.w};
        #pragma unroll
        for (int k = 0; k < 4; ++k)
            h[k] = fmaf(mm[k], fmaf(-Br, mm[k], Ar),
                         fmaf(Bp, uu[k], h[k]));
    }

    stcs4(&out4[i], make_float4(h[0], h[1], h[2], h[3]));
}

extern "C" void kernel_launch(void* const* d_in, const int* in_sizes, int n_in,
                              void* d_out, int out_size) {
    const float* chem = (const float*)d_in[0];
    const float* mu   = (const float*)d_in[1];
    const float* vu   = (const float*)d_in[2];
    const float* Q    = (const float*)d_in[3];
    const float* Ks   = (const float*)d_in[4];
    const float* v    = (const float*)d_in[5];
    const float* y    = (const float*)d_in[6];
    const float* z    = (const float*)d_in[7];
    const int*   t    = (const int*)d_in[8];
    float* out = (float*)d_out;

    int quads = out_size / 4;   // M*N / 4 = 524288
    int threads = 256;
    int blocks = (quads + threads - 1) / threads;  // 2048, one quad/thread

    rnn_fused_kernel<<<blocks, threads>>>(chem, mu, vu, Q, Ks, v, y, z, t,
                                          out, quads);
}

// round 6
// speedup vs baseline: 1.5318x; 1.5318x over previous
#include <cuda_runtime.h>

#define NC 5
#define NR 14
#define NG 7   // rule groups of 2 rules each

__device__ __forceinline__ float fast_tanh(float x) {
    float r;
    asm("tanh.approx.f32 %0, %1;" : "=f"(r) : "f"(x));
    return r;
}

__device__ __forceinline__ float4 ldcs4(const float4* p) {
    float4 r;
    asm("ld.global.cs.v4.f32 {%0,%1,%2,%3}, [%4];"
        : "=f"(r.x), "=f"(r.y), "=f"(r.z), "=f"(r.w) : "l"(p));
    return r;
}

__device__ __forceinline__ void stcs4(float4* p, float4 v) {
    asm("st.global.cs.v4.f32 [%0], {%1,%2,%3,%4};"
        :: "l"(p), "f"(v.x), "f"(v.y), "f"(v.z), "f"(v.w) : "memory");
}

__global__ __launch_bounds__(256, 4) void rnn_fused_kernel(
    const float* __restrict__ chem,   // [C, M*N]
    const float* __restrict__ mu,     // [R, M*N]
    const float* __restrict__ vu,     // [R, M*N]
    const float* __restrict__ Q,      // [C, 2R]
    const float* __restrict__ Ks,     // [C, C]
    const float* __restrict__ v,      // [1, C]
    const float* __restrict__ y,      // [C]
    const float* __restrict__ z,      // [C]
    const int*   __restrict__ tptr,   // scalar time_index
    float* __restrict__ out,          // [M*N]
    int quads)                        // M*N / 4
{
    __shared__ float sA[NR], sB[NR], sBp[NR];
    __shared__ float sa[NC], sw[NC], sK[NC * NC];

    if (threadIdx.x == 0) {
        float invt = 1.0f / (float)(*tptr);
        float wreg[NC];
        #pragma unroll
        for (int c = 0; c < NC; ++c) {
            float vc = v[c];
            sa[c] = vc * y[c];
            wreg[c] = vc * z[c];
            sw[c] = wreg[c];
        }
        #pragma unroll
        for (int c = 0; c < NC; ++c)
            #pragma unroll
            for (int d = 0; d < NC; ++d)
                sK[c * NC + d] = Ks[c * NC + d];
        #pragma unroll
        for (int r = 0; r < NR; ++r) {
            float A = 0.0f, B = 0.0f;
            #pragma unroll
            for (int c = 0; c < NC; ++c) {
                A = fmaf(wreg[c], Q[c * (2 * NR) + r], A);
                B = fmaf(wreg[c], Q[c * (2 * NR) + NR + r], B);
            }
            sA[r] = A;
            sB[r] = B;
            sBp[r] = B * invt;
        }
    }
    __syncthreads();

    const float4* ch4 = (const float4*)chem;
    const float4* mu4 = (const float4*)mu;
    const float4* vu4 = (const float4*)vu;
    float4* out4 = (float4*)out;

    const int stride = gridDim.x * blockDim.x;

    for (int i = blockIdx.x * blockDim.x + threadIdx.x; i < quads;
         i += stride) {

        // (1) Issue ALL chem loads now; consumed last -> latency fully hidden
        //     behind the rule pipeline below.
        float4 cv[NC];
        #pragma unroll
        for (int c = 0; c < NC; ++c)
            cv[c] = ldcs4(&ch4[c * quads + i]);

        // (2) Rule loop, explicit double-buffered prefetch, 2 rules/group.
        float4 mb[2][2], ub[2][2];
        mb[0][0] = ldcs4(&mu4[0 * quads + i]);
        mb[0][1] = ldcs4(&mu4[1 * quads + i]);
        ub[0][0] = ldcs4(&vu4[0 * quads + i]);
        ub[0][1] = ldcs4(&vu4[1 * quads + i]);

        float h[4] = {0.f, 0.f, 0.f, 0.f};

        #pragma unroll
        for (int g = 0; g < NG; ++g) {
            const int cb = g & 1, nb = cb ^ 1;
            if (g < NG - 1) {
                const int r = 2 * (g + 1);
                mb[nb][0] = ldcs4(&mu4[(r    ) * quads + i]);
                mb[nb][1] = ldcs4(&mu4[(r + 1) * quads + i]);
                ub[nb][0] = ldcs4(&vu4[(r    ) * quads + i]);
                ub[nb][1] = ldcs4(&vu4[(r + 1) * quads + i]);
            }
            #pragma unroll
            for (int j = 0; j < 2; ++j) {
                const int r = 2 * g + j;
                const float Ar = sA[r], Br = sB[r], Bp = sBp[r];
                const float4 m = mb[cb][j];
                const float4 u = ub[cb][j];
                const float mm[4] = {m.x, m.y, m.z, m.w};
                const float uu[4] = {u.x, u.y, u.z, u.w};
                #pragma unroll
                for (int k = 0; k < 4; ++k)
                    h[k] = fmaf(mm[k], fmaf(-Br, mm[k], Ar),
                                 fmaf(Bp, uu[k], h[k]));
            }
        }

        // (3) Chemical part: cv[] arrived long ago.
        //     h += a_c * chem_c + w_c * tanh(K @ chem)
        const float x0[NC] = {cv[0].x, cv[1].x, cv[2].x, cv[3].x, cv[4].x};
        const float x1[NC] = {cv[0].y, cv[1].y, cv[2].y, cv[3].y, cv[4].y};
        const float x2[NC] = {cv[0].z, cv[1].z, cv[2].z, cv[3].z, cv[4].z};
        const float x3[NC] = {cv[0].w, cv[1].w, cv[2].w, cv[3].w, cv[4].w};

        #pragma unroll
        for (int c = 0; c < NC; ++c) {
            float t0 = 0.f, t1 = 0.f, t2 = 0.f, t3 = 0.f;
            #pragma unroll
            for (int d = 0; d < NC; ++d) {
                const float kcd = sK[c * NC + d];
                t0 = fmaf(kcd, x0[d], t0);
                t1 = fmaf(kcd, x1[d], t1);
                t2 = fmaf(kcd, x2[d], t2);
                t3 = fmaf(kcd, x3[d], t3);
            }
            const float ac = sa[c], wc = sw[c];
            h[0] = fmaf(ac, x0[c], fmaf(wc, fast_tanh(t0), h[0]));
            h[1] = fmaf(ac, x1[c], fmaf(wc, fast_tanh(t1), h[1]));
            h[2] = fmaf(ac, x2[c], fmaf(wc, fast_tanh(t2), h[2]));
            h[3] = fmaf(ac, x3[c], fmaf(wc, fast_tanh(t3), h[3]));
        }

        stcs4(&out4[i], make_float4(h[0], h[1], h[2], h[3]));
    }
}

extern "C" void kernel_launch(void* const* d_in, const int* in_sizes, int n_in,
                              void* d_out, int out_size) {
    const float* chem = (const float*)d_in[0];
    const float* mu   = (const float*)d_in[1];
    const float* vu   = (const float*)d_in[2];
    const float* Q    = (const float*)d_in[3];
    const float* Ks   = (const float*)d_in[4];
    const float* v    = (const float*)d_in[5];
    const float* y    = (const float*)d_in[6];
    const float* z    = (const float*)d_in[7];
    const int*   t    = (const int*)d_in[8];
    float* out = (float*)d_out;

    int quads = out_size / 4;   // M*N / 4 = 524288
    int threads = 256;
    int blocks = (quads + threads - 1) / threads;
    int persistent = 152 * 4;   // GB300: 152 SMs x 4 CTAs/SM
    if (blocks > persistent) blocks = persistent;

    rnn_fused_kernel<<<blocks, threads>>>(chem, mu, vu, Q, Ks, v, y, z, t,
                                          out, quads);
}